// round 16
// baseline (speedup 1.0000x reference)
#include <cuda_runtime.h>
#include <cuda_bf16.h>
#include <cstdint>

// Problem constants (fixed by the dataset)
#define NN 50000
#define DH 128
#define EE 800000
#define KK 256
#define GG 391            // GEMM CTAs per mode
#define GATHER_CTAS 782   // 64 nodes per CTA

// ---------------------------------------------------------------------------
// Scratch device globals. Referenced ONLY from device code (host-shadow bug!).
// x/h_prev consumed directly by tf32 GEMMs (HW-truncated tf32; budgeted).
// rh stored rna-rounded tf32 bits. Weights n-major: g_WB[mode][n][k].
// g_ybf: y stored bf16. g_flag[i]: rh rows [128i,128(i+1)) ready.
// g_done: count of completed mode-2 (y) CTAs.
// ---------------------------------------------------------------------------
__device__ uint32_t g_rh32[NN * DH];
__device__ uint32_t g_WB  [4 * KK * DH];
__device__ float g_z  [NN * DH];
__device__ __nv_bfloat16 g_ybf[NN * DH];
__device__ float g_w  [NN * DH];
__device__ float g_agg[NN * DH];
__device__ int g_flag[512];
__device__ int g_done;
// CSR for gather
__device__ int g_deg[NN];
__device__ int g_cur[NN];
__device__ int g_off[NN];
__device__ int g_csr[EE];

__device__ __forceinline__ float sigmoidf_(float v) {
    return 1.0f / (1.0f + __expf(-v));
}
__device__ __forceinline__ uint32_t f2tf32(float f) {
    uint32_t r;
    asm("cvt.rna.tf32.f32 %0, %1;" : "=r"(r) : "f"(f));
    return r;
}
__device__ __forceinline__ void cpasync16(uint32_t dst, const void* src, int sz) {
    asm volatile("cp.async.ca.shared.global [%0], [%1], 16, %2;"
                 :: "r"(dst), "l"(src), "r"(sz));
}
__device__ __forceinline__ void mma_tf32(float c[4], uint32_t a0, uint32_t a1,
                                         uint32_t a2, uint32_t a3,
                                         uint32_t b0, uint32_t b1) {
    asm volatile(
        "mma.sync.aligned.m16n8k8.row.col.f32.tf32.tf32.f32 "
        "{%0,%1,%2,%3}, {%4,%5,%6,%7}, {%8,%9}, {%0,%1,%2,%3};"
        : "+f"(c[0]), "+f"(c[1]), "+f"(c[2]), "+f"(c[3])
        : "r"(a0), "r"(a1), "r"(a2), "r"(a3), "r"(b0), "r"(b1));
}

// ---------------------------------------------------------------------------
// Prep W: transpose to [mode][n][k] tf32 (rna) via smem tile.
// Also zeroes g_flag and g_done (graph-replay safe; runs before mega kernel).
// ---------------------------------------------------------------------------
__global__ void prep_w(
    const float* __restrict__ W_xr, const float* __restrict__ W_hr,
    const float* __restrict__ W_xz, const float* __restrict__ W_hz,
    const float* __restrict__ W_l,  const float* __restrict__ W_r)
{
    __shared__ float s[32][33];
    const int kb = blockIdx.x, nb = blockIdx.y, mode = blockIdx.z;
    const int tx = threadIdx.x, ty = threadIdx.y;

    if (kb == 0 && nb == 0 && mode == 0) {
        const int t = ty * 32 + tx;
        if (t < 512) g_flag[t] = 0;
        if (t == 0)  g_done = 0;
    }

#pragma unroll
    for (int r = 0; r < 4; r++) {
        const int k = kb * 32 + ty + r * 8;
        const int n = nb * 32 + tx;
        float v;
        if (mode == 0)      v = (k < 128) ? W_xr[k * DH + n] : W_hr[(k - 128) * DH + n];
        else if (mode == 1) v = (k < 128) ? W_xz[k * DH + n] : W_hz[(k - 128) * DH + n];
        else if (mode == 2) v = W_l[k * DH + n];
        else                v = W_r[k * DH + n];
        s[ty + r * 8][tx] = v;
    }
    __syncthreads();
#pragma unroll
    for (int r = 0; r < 4; r++) {
        const int n = nb * 32 + ty + r * 8;
        const int k = kb * 32 + tx;
        g_WB[(size_t)mode * KK * DH + n * KK + k] = f2tf32(s[tx][ty + r * 8]);
    }
}

// ---------------------------------------------------------------------------
// CSR build: zero -> histogram -> single-block scan -> bucket fill
// ---------------------------------------------------------------------------
__global__ __launch_bounds__(256) void zero_dc()
{
    const int i = blockIdx.x * blockDim.x + threadIdx.x;
    if (i < NN) { g_deg[i] = 0; g_cur[i] = 0; }
}
__global__ __launch_bounds__(256) void hist_kernel(const int* __restrict__ ei)
{
    const int i = blockIdx.x * blockDim.x + threadIdx.x;
    if (i < EE) atomicAdd(&g_deg[ei[EE + i]], 1);
}
__global__ __launch_bounds__(1024) void scan_kernel()
{
    __shared__ int part[1024];
    const int t = threadIdx.x;
    const int CH = (NN + 1023) / 1024;   // 49
    const int base = t * CH;
    int s = 0;
    for (int i = 0; i < CH; i++) {
        const int idx = base + i;
        if (idx < NN) s += g_deg[idx];
    }
    part[t] = s;
    __syncthreads();
    for (int d = 1; d < 1024; d <<= 1) {
        int v = (t >= d) ? part[t - d] : 0;
        __syncthreads();
        part[t] += v;
        __syncthreads();
    }
    int run = (t == 0) ? 0 : part[t - 1];
    for (int i = 0; i < CH; i++) {
        const int idx = base + i;
        if (idx < NN) { g_off[idx] = run; run += g_deg[idx]; }
    }
}
__global__ __launch_bounds__(256) void fill_kernel(const int* __restrict__ ei)
{
    const int i = blockIdx.x * blockDim.x + threadIdx.x;
    if (i >= EE) return;
    const int dst = ei[EE + i];
    const int pos = atomicAdd(&g_cur[dst], 1);
    g_csr[g_off[dst] + pos] = ei[i];
}

// ---------------------------------------------------------------------------
// MEGA kernel, 1D grid of 4*GG + GATHER_CTAS CTAs:
//   bx in [0, 4*GG):        GEMM region, mode = bx/GG, mx = bx%GG.
//     mode 0: [x|h]  @ WB0 -> rh + release flag[mx]
//     mode 1: [x|h]  @ WB1 -> z
//     mode 2: [x|rh] @ WB2 -> y (bf16)  (acquire flag[mx] at K-chunk 8)
//             + completion count into g_done
//     mode 3: [x|rh] @ WB3 -> w         (acquire flag[mx] at K-chunk 8)
//   bx >= 4*GG:             GATHER region: spin until g_done==GG, then
//     sum neighbor y rows -> g_agg. Overlaps the mode-3 drain tail.
// Deadlock-free: CTA dispatch monotonic in linear id (validated R15), so all
// producers are dispatched before any dependent consumer.
// ---------------------------------------------------------------------------
#define AP 20
#define BP 20
#define ST 3

__global__ __launch_bounds__(256, 2) void mega_kernel(
    const uint32_t* __restrict__ xp, const uint32_t* __restrict__ hp,
    const float* __restrict__ bias_r, const float* __restrict__ bias_z,
    const float* __restrict__ hprev, int Nrows)
{
    const int bx  = blockIdx.x;
    const int tid = threadIdx.x;

    // ---------------- GATHER region ----------------
    if (bx >= 4 * GG) {
        if (tid == 0) {
            int v;
            for (;;) {
                asm volatile("ld.global.acquire.gpu.b32 %0, [%1];"
                             : "=r"(v) : "l"(&g_done));
                if (v >= GG) break;
                __nanosleep(200);
            }
        }
        __syncthreads();

        const int wid  = tid >> 5;
        const int lane = tid & 31;
        const int nbase = (bx - 4 * GG) * 64 + wid * 8;
#pragma unroll 1
        for (int i = 0; i < 8; i++) {
            const int node = nbase + i;
            if (node >= NN) break;
            const int off = g_off[node];
            const int deg = g_deg[node];
            float4 acc = make_float4(0.f, 0.f, 0.f, 0.f);
            auto addrow = [&](int s) {
                const uint2 v = *(const uint2*)&g_ybf[(size_t)s * DH + lane * 4];
                const float2 p0 = __bfloat1622float2(*(const __nv_bfloat162*)&v.x);
                const float2 p1 = __bfloat1622float2(*(const __nv_bfloat162*)&v.y);
                acc.x += p0.x; acc.y += p0.y; acc.z += p1.x; acc.w += p1.y;
            };
            int e = 0;
            for (; e + 4 <= deg; e += 4) {
                const int s0 = g_csr[off + e + 0];
                const int s1 = g_csr[off + e + 1];
                const int s2 = g_csr[off + e + 2];
                const int s3 = g_csr[off + e + 3];
                addrow(s0); addrow(s1); addrow(s2); addrow(s3);
            }
            for (; e < deg; e++) addrow(g_csr[off + e]);
            *(float4*)&g_agg[(size_t)node * DH + lane * 4] = acc;
        }
        return;
    }

    // ---------------- GEMM region ----------------
    __shared__ uint32_t As[ST][128 * AP];
    __shared__ uint32_t Bs[ST][128 * BP];

    const int mode = bx / GG;       // CTA-uniform
    const int mx   = bx % GG;
    const uint32_t* A0 = xp;
    const uint32_t* A1 = (mode >= 2) ? (const uint32_t*)g_rh32 : hp;
    const uint32_t* B  = g_WB + (size_t)mode * (KK * DH);

    const int lane = tid & 31;
    const int wid  = tid >> 5;
    const int row0 = mx * 128;
    const int wm   = (wid >> 2) * 64;
    const int wn   = (wid & 3) * 32;
    const int g    = lane >> 2;
    const int t    = lane & 3;

    float acc[4][4][4];
#pragma unroll
    for (int mi = 0; mi < 4; mi++)
#pragma unroll
        for (int ni = 0; ni < 4; ni++)
#pragma unroll
            for (int q = 0; q < 4; q++) acc[mi][ni][q] = 0.0f;

    auto stage = [&](int c, int buf) {
        const int k0 = c * 16;
        const uint32_t* Asrc = (k0 < 128) ? A0 : A1;
        const int ka = k0 & 127;
#pragma unroll
        for (int i = 0; i < 2; i++) {      // A: 128 rows x 16 words
            const int id  = tid + i * 256;
            const int row = id >> 2;
            const int kq  = (id & 3) * 4;
            const uint32_t dst = (uint32_t)__cvta_generic_to_shared(
                &As[buf][row * AP + kq]);
            const int sz = (row0 + row < Nrows) ? 16 : 0;
            cpasync16(dst, &Asrc[(size_t)(row0 + row) * DH + ka + kq], sz);
        }
#pragma unroll
        for (int i = 0; i < 2; i++) {      // B: 128 n x 16 words
            const int id = tid + i * 256;
            const int n  = id >> 2;
            const int kq = (id & 3) * 4;
            const uint32_t dst = (uint32_t)__cvta_generic_to_shared(
                &Bs[buf][n * BP + kq]);
            cpasync16(dst, &B[(size_t)n * KK + k0 + kq], 16);
        }
        asm volatile("cp.async.commit_group;");
    };

    stage(0, 0);
    stage(1, 1);

#pragma unroll 1
    for (int c = 0; c < 16; c++) {
        if (c < 15) { asm volatile("cp.async.wait_group 1;"); }
        else        { asm volatile("cp.async.wait_group 0;"); }
        __syncthreads();   // also fences: chunk c-1 reads done -> buf (c+2)%ST free

        // rh dependency: modes 2/3 must not stage K-chunk 8 until producer
        // (mode 0, same mx) released the flag.
        if (mode >= 2 && c == 6) {
            if (tid == 0) {
                int v;
                do {
                    asm volatile("ld.global.acquire.gpu.b32 %0, [%1];"
                                 : "=r"(v) : "l"(&g_flag[mx]));
                } while (v == 0);
            }
            __syncthreads();
        }

        if (c + 2 < 16) stage(c + 2, (c + 2) % ST);

        const int buf = c % ST;
#pragma unroll
        for (int k8 = 0; k8 < 2; k8++) {
            const int kk = k8 * 8;
            uint32_t a[4][4], b[4][2];
#pragma unroll
            for (int mi = 0; mi < 4; mi++) {
                const int rb = wm + mi * 16 + g;
                a[mi][0] = As[buf][(rb)     * AP + kk + t];
                a[mi][1] = As[buf][(rb + 8) * AP + kk + t];
                a[mi][2] = As[buf][(rb)     * AP + kk + t + 4];
                a[mi][3] = As[buf][(rb + 8) * AP + kk + t + 4];
            }
#pragma unroll
            for (int ni = 0; ni < 4; ni++) {
                const int cb = wn + ni * 8 + g;
                b[ni][0] = Bs[buf][cb * BP + kk + t];
                b[ni][1] = Bs[buf][cb * BP + kk + t + 4];
            }
#pragma unroll
            for (int mi = 0; mi < 4; mi++)
#pragma unroll
                for (int ni = 0; ni < 4; ni++)
                    mma_tf32(acc[mi][ni], a[mi][0], a[mi][1], a[mi][2], a[mi][3],
                             b[ni][0], b[ni][1]);
        }
    }

    // epilogue: thread owns (row = wm+mi*16+g(+8), cols = wn+ni*8+2t, +1)
#pragma unroll
    for (int mi = 0; mi < 4; mi++) {
#pragma unroll
        for (int half = 0; half < 2; half++) {
            const int grow = row0 + wm + mi * 16 + g + half * 8;
            if (grow >= Nrows) continue;
#pragma unroll
            for (int ni = 0; ni < 4; ni++) {
                const int col = wn + ni * 8 + 2 * t;
                float c0 = acc[mi][ni][half * 2 + 0];
                float c1 = acc[mi][ni][half * 2 + 1];
                const size_t off = (size_t)grow * DH + col;
                if (mode == 0) {
                    c0 = sigmoidf_(c0 + bias_r[col]);
                    c1 = sigmoidf_(c1 + bias_r[col + 1]);
                    const float2 hh = *(const float2*)&hprev[off];
                    uint2 o;
                    o.x = f2tf32(c0 * hh.x);
                    o.y = f2tf32(c1 * hh.y);
                    *(uint2*)&g_rh32[off] = o;
                } else if (mode == 1) {
                    float2 o;
                    o.x = sigmoidf_(c0 + bias_z[col]);
                    o.y = sigmoidf_(c1 + bias_z[col + 1]);
                    *(float2*)&g_z[off] = o;
                } else if (mode == 2) {
                    __nv_bfloat162 p;
                    p.x = __float2bfloat16_rn(c0);
                    p.y = __float2bfloat16_rn(c1);
                    *(__nv_bfloat162*)&g_ybf[off] = p;
                } else {
                    *(float2*)&g_w[off] = make_float2(c0, c1);
                }
            }
        }
    }

    if (mode == 0) {
        // publish rh rows for this mx
        __syncthreads();
        if (tid == 0) {
            asm volatile("st.global.release.gpu.b32 [%0], %1;"
                         :: "l"(&g_flag[mx]), "r"(1));
        }
    } else if (mode == 2) {
        // count y completion (canonical fence+sync+atomic pattern)
        __threadfence();
        __syncthreads();
        if (tid == 0) atomicAdd(&g_done, 1);
    }
}

// ---------------------------------------------------------------------------
// Final: out = (1-z) * (agg/max(deg,1) + b_l + w) + z * h_prev
// ---------------------------------------------------------------------------
__global__ __launch_bounds__(256) void final_kernel(
    const float* __restrict__ hprev, const float* __restrict__ b_l,
    float* __restrict__ out)
{
    const int i4 = blockIdx.x * blockDim.x + threadIdx.x;   // over NN*32
    if (i4 >= NN * (DH / 4)) return;
    const int node = i4 >> 5;
    const int c4   = i4 & 31;
    const size_t off = (size_t)i4 * 4;

    const float inv = 1.0f / (float)max(g_deg[node], 1);
    const float4 a  = *(const float4*)&g_agg[off];
    const float4 w  = *(const float4*)&g_w[off];
    const float4 z  = *(const float4*)&g_z[off];
    const float4 hh = *(const float4*)&hprev[off];
    const float4 bl = *(const float4*)&b_l[c4 * 4];

    float4 o;
    float n;
    n = fmaf(a.x, inv, bl.x) + w.x; o.x = (1.0f - z.x) * n + z.x * hh.x;
    n = fmaf(a.y, inv, bl.y) + w.y; o.y = (1.0f - z.y) * n + z.y * hh.y;
    n = fmaf(a.z, inv, bl.z) + w.z; o.z = (1.0f - z.z) * n + z.z * hh.z;
    n = fmaf(a.w, inv, bl.w) + w.w; o.w = (1.0f - z.w) * n + z.w * hh.w;
    *(float4*)&out[off] = o;
}

// ---------------------------------------------------------------------------
extern "C" void kernel_launch(void* const* d_in, const int* in_sizes, int n_in,
                              void* d_out, int out_size)
{
    const float* x    = (const float*)d_in[0];
    const int*   ei   = (const int*)  d_in[1];
    const float* h    = (const float*)d_in[2];
    const float* W_xr = (const float*)d_in[3];
    const float* b_xr = (const float*)d_in[4];
    const float* W_hr = (const float*)d_in[5];
    const float* W_xz = (const float*)d_in[6];
    const float* b_xz = (const float*)d_in[7];
    const float* W_hz = (const float*)d_in[8];
    const float* W_l  = (const float*)d_in[9];
    const float* b_l  = (const float*)d_in[10];
    const float* W_r  = (const float*)d_in[11];
    float* out = (float*)d_out;

    const uint32_t* xu = (const uint32_t*)x;
    const uint32_t* hu = (const uint32_t*)h;

    // One-time resources (created on the first, non-captured, call)
    static cudaStream_t sC = nullptr;
    static cudaEvent_t evRoot, evC;
    if (!sC) {
        cudaStreamCreateWithFlags(&sC, cudaStreamNonBlocking);
        cudaEventCreateWithFlags(&evRoot, cudaEventDisableTiming);
        cudaEventCreateWithFlags(&evC,    cudaEventDisableTiming);
    }

    // Fork: CSR build hidden on side stream (gather region needs it before
    // g_done releases, which is far later than this ~45us chain).
    cudaEventRecord(evRoot, 0);
    cudaStreamWaitEvent(sC, evRoot, 0);
    zero_dc<<<(NN + 255) / 256, 256, 0, sC>>>();
    hist_kernel<<<(EE + 255) / 256, 256, 0, sC>>>(ei);
    scan_kernel<<<1, 1024, 0, sC>>>();
    fill_kernel<<<(EE + 255) / 256, 256, 0, sC>>>(ei);
    cudaEventRecord(evC, sC);

    // Main stream: prep (zeroes flags+counter) -> join CSR -> mega kernel
    prep_w<<<dim3(8, 4, 4), dim3(32, 8)>>>(W_xr, W_hr, W_xz, W_hz, W_l, W_r);
    cudaStreamWaitEvent(0, evC, 0);
    mega_kernel<<<4 * GG + GATHER_CTAS, 256>>>(xu, hu, b_xr, b_xz, h, NN);

    // Final elementwise combine
    final_kernel<<<(NN * (DH / 4) + 255) / 256, 256>>>(h, b_l, out);
}

// round 17
// speedup vs baseline: 1.3665x; 1.3665x over previous
#include <cuda_runtime.h>
#include <cuda_bf16.h>
#include <cstdint>

// Problem constants (fixed by the dataset)
#define NN 50000
#define DH 128
#define EE 800000
#define KK 256
#define GG 391            // GEMM CTAs per mode

// ---------------------------------------------------------------------------
// Scratch device globals. Referenced ONLY from device code (host-shadow bug!).
// x/h_prev consumed directly by tf32 GEMMs (HW-truncated tf32; budgeted).
// rh stored rna-rounded tf32 bits. Weights n-major: g_WB[mode][n][k].
// g_ybf: y stored bf16. g_flag[i]: rh rows [128i,128(i+1)) ready.
// ---------------------------------------------------------------------------
__device__ uint32_t g_rh32[NN * DH];
__device__ uint32_t g_WB  [4 * KK * DH];
__device__ float g_z  [NN * DH];
__device__ __nv_bfloat16 g_ybf[NN * DH];
__device__ float g_w  [NN * DH];
__device__ float g_agg[NN * DH];
__device__ int g_flag[512];
// CSR for gather
__device__ int g_deg[NN];
__device__ int g_cur[NN];
__device__ int g_off[NN];
__device__ int g_csr[EE];

__device__ __forceinline__ float sigmoidf_(float v) {
    return 1.0f / (1.0f + __expf(-v));
}
__device__ __forceinline__ uint32_t f2tf32(float f) {
    uint32_t r;
    asm("cvt.rna.tf32.f32 %0, %1;" : "=r"(r) : "f"(f));
    return r;
}
__device__ __forceinline__ void cpasync16(uint32_t dst, const void* src, int sz) {
    asm volatile("cp.async.ca.shared.global [%0], [%1], 16, %2;"
                 :: "r"(dst), "l"(src), "r"(sz));
}
__device__ __forceinline__ void mma_tf32(float c[4], uint32_t a0, uint32_t a1,
                                         uint32_t a2, uint32_t a3,
                                         uint32_t b0, uint32_t b1) {
    asm volatile(
        "mma.sync.aligned.m16n8k8.row.col.f32.tf32.tf32.f32 "
        "{%0,%1,%2,%3}, {%4,%5,%6,%7}, {%8,%9}, {%0,%1,%2,%3};"
        : "+f"(c[0]), "+f"(c[1]), "+f"(c[2]), "+f"(c[3])
        : "r"(a0), "r"(a1), "r"(a2), "r"(a3), "r"(b0), "r"(b1));
}

// ---------------------------------------------------------------------------
// Prep W: transpose to [mode][n][k] tf32 (rna) via smem tile.
// Also zeroes g_flag (runs on main stream before the GEMMs).
// ---------------------------------------------------------------------------
__global__ void prep_w(
    const float* __restrict__ W_xr, const float* __restrict__ W_hr,
    const float* __restrict__ W_xz, const float* __restrict__ W_hz,
    const float* __restrict__ W_l,  const float* __restrict__ W_r)
{
    __shared__ float s[32][33];
    const int kb = blockIdx.x, nb = blockIdx.y, mode = blockIdx.z;
    const int tx = threadIdx.x, ty = threadIdx.y;

    if (kb == 0 && nb == 0 && mode == 0) {
        const int t = ty * 32 + tx;
        if (t < 512) g_flag[t] = 0;
    }

#pragma unroll
    for (int r = 0; r < 4; r++) {
        const int k = kb * 32 + ty + r * 8;
        const int n = nb * 32 + tx;
        float v;
        if (mode == 0)      v = (k < 128) ? W_xr[k * DH + n] : W_hr[(k - 128) * DH + n];
        else if (mode == 1) v = (k < 128) ? W_xz[k * DH + n] : W_hz[(k - 128) * DH + n];
        else if (mode == 2) v = W_l[k * DH + n];
        else                v = W_r[k * DH + n];
        s[ty + r * 8][tx] = v;
    }
    __syncthreads();
#pragma unroll
    for (int r = 0; r < 4; r++) {
        const int n = nb * 32 + ty + r * 8;
        const int k = kb * 32 + tx;
        g_WB[(size_t)mode * KK * DH + n * KK + k] = f2tf32(s[tx][ty + r * 8]);
    }
}

// ---------------------------------------------------------------------------
// CSR build: zero -> histogram -> single-block scan -> bucket fill
// ---------------------------------------------------------------------------
__global__ __launch_bounds__(256) void zero_dc()
{
    const int i = blockIdx.x * blockDim.x + threadIdx.x;
    if (i < NN) { g_deg[i] = 0; g_cur[i] = 0; }
}
__global__ __launch_bounds__(256) void hist_kernel(const int* __restrict__ ei)
{
    const int i = blockIdx.x * blockDim.x + threadIdx.x;
    if (i < EE) atomicAdd(&g_deg[ei[EE + i]], 1);
}
__global__ __launch_bounds__(1024) void scan_kernel()
{
    __shared__ int part[1024];
    const int t = threadIdx.x;
    const int CH = (NN + 1023) / 1024;   // 49
    const int base = t * CH;
    int s = 0;
    for (int i = 0; i < CH; i++) {
        const int idx = base + i;
        if (idx < NN) s += g_deg[idx];
    }
    part[t] = s;
    __syncthreads();
    for (int d = 1; d < 1024; d <<= 1) {
        int v = (t >= d) ? part[t - d] : 0;
        __syncthreads();
        part[t] += v;
        __syncthreads();
    }
    int run = (t == 0) ? 0 : part[t - 1];
    for (int i = 0; i < CH; i++) {
        const int idx = base + i;
        if (idx < NN) { g_off[idx] = run; run += g_deg[idx]; }
    }
}
__global__ __launch_bounds__(256) void fill_kernel(const int* __restrict__ ei)
{
    const int i = blockIdx.x * blockDim.x + threadIdx.x;
    if (i >= EE) return;
    const int dst = ei[EE + i];
    const int pos = atomicAdd(&g_cur[dst], 1);
    g_csr[g_off[dst] + pos] = ei[i];
}

// ---------------------------------------------------------------------------
// TF32 GEMM, mode = BASE + blockIdx.y (CTA-uniform):
//   mode 0: [x|h]  @ WB0 -> rh (tf32 bits) + release flag[mx]
//   mode 1: [x|h]  @ WB1 -> z
//   mode 2: [x|rh] @ WB2 -> y (bf16)   (acquire flag[mx] at K-chunk 8)
//   mode 3: [x|rh] @ WB3 -> w          (flag already 1: launch-order dep)
// Launch A: BASE=0 grid(391,3) — handshake topology validated in R15.
// Launch B: BASE=3 grid(391,1).
// Mainloop = champion shape (BM=128 BN=128 BK=16, 8 warps 64x32, 3-stage).
// ---------------------------------------------------------------------------
#define AP 20
#define BP 20
#define ST 3

template <int BASE>
__global__ __launch_bounds__(256, 2) void gemm_modes(
    const uint32_t* __restrict__ xp, const uint32_t* __restrict__ hp,
    const float* __restrict__ bias_r, const float* __restrict__ bias_z,
    const float* __restrict__ hprev, int Nrows)
{
    __shared__ uint32_t As[ST][128 * AP];
    __shared__ uint32_t Bs[ST][128 * BP];

    const int mode = BASE + blockIdx.y;              // CTA-uniform
    const int mx   = blockIdx.x;
    const uint32_t* A0 = xp;
    const uint32_t* A1 = (mode >= 2) ? (const uint32_t*)g_rh32 : hp;
    const uint32_t* B  = g_WB + (size_t)mode * (KK * DH);

    const int tid  = threadIdx.x;
    const int lane = tid & 31;
    const int wid  = tid >> 5;
    const int row0 = mx * 128;
    const int wm   = (wid >> 2) * 64;
    const int wn   = (wid & 3) * 32;
    const int g    = lane >> 2;
    const int t    = lane & 3;

    float acc[4][4][4];
#pragma unroll
    for (int mi = 0; mi < 4; mi++)
#pragma unroll
        for (int ni = 0; ni < 4; ni++)
#pragma unroll
            for (int q = 0; q < 4; q++) acc[mi][ni][q] = 0.0f;

    auto stage = [&](int c, int buf) {
        const int k0 = c * 16;
        const uint32_t* Asrc = (k0 < 128) ? A0 : A1;
        const int ka = k0 & 127;
#pragma unroll
        for (int i = 0; i < 2; i++) {      // A: 128 rows x 16 words
            const int id  = tid + i * 256;
            const int row = id >> 2;
            const int kq  = (id & 3) * 4;
            const uint32_t dst = (uint32_t)__cvta_generic_to_shared(
                &As[buf][row * AP + kq]);
            const int sz = (row0 + row < Nrows) ? 16 : 0;
            cpasync16(dst, &Asrc[(size_t)(row0 + row) * DH + ka + kq], sz);
        }
#pragma unroll
        for (int i = 0; i < 2; i++) {      // B: 128 n x 16 words
            const int id = tid + i * 256;
            const int n  = id >> 2;
            const int kq = (id & 3) * 4;
            const uint32_t dst = (uint32_t)__cvta_generic_to_shared(
                &Bs[buf][n * BP + kq]);
            cpasync16(dst, &B[(size_t)n * KK + k0 + kq], 16);
        }
        asm volatile("cp.async.commit_group;");
    };

    stage(0, 0);
    stage(1, 1);

#pragma unroll 1
    for (int c = 0; c < 16; c++) {
        if (c < 15) { asm volatile("cp.async.wait_group 1;"); }
        else        { asm volatile("cp.async.wait_group 0;"); }
        __syncthreads();   // also fences: chunk c-1 reads done -> buf (c+2)%ST free

        // rh dependency: modes 2/3 must not stage K-chunk 8 until producer
        // (mode 0, same mx) released the flag. For BASE=3 the flag is already
        // set (launch A completed by stream order) -> passes immediately.
        if (mode >= 2 && c == 6) {
            if (tid == 0) {
                int v;
                do {
                    asm volatile("ld.global.acquire.gpu.b32 %0, [%1];"
                                 : "=r"(v) : "l"(&g_flag[mx]));
                } while (v == 0);
            }
            __syncthreads();
        }

        if (c + 2 < 16) stage(c + 2, (c + 2) % ST);

        const int buf = c % ST;
#pragma unroll
        for (int k8 = 0; k8 < 2; k8++) {
            const int kk = k8 * 8;
            uint32_t a[4][4], b[4][2];
#pragma unroll
            for (int mi = 0; mi < 4; mi++) {
                const int rb = wm + mi * 16 + g;
                a[mi][0] = As[buf][(rb)     * AP + kk + t];
                a[mi][1] = As[buf][(rb + 8) * AP + kk + t];
                a[mi][2] = As[buf][(rb)     * AP + kk + t + 4];
                a[mi][3] = As[buf][(rb + 8) * AP + kk + t + 4];
            }
#pragma unroll
            for (int ni = 0; ni < 4; ni++) {
                const int cb = wn + ni * 8 + g;
                b[ni][0] = Bs[buf][cb * BP + kk + t];
                b[ni][1] = Bs[buf][cb * BP + kk + t + 4];
            }
#pragma unroll
            for (int mi = 0; mi < 4; mi++)
#pragma unroll
                for (int ni = 0; ni < 4; ni++)
                    mma_tf32(acc[mi][ni], a[mi][0], a[mi][1], a[mi][2], a[mi][3],
                             b[ni][0], b[ni][1]);
        }
    }

    // epilogue: thread owns (row = wm+mi*16+g(+8), cols = wn+ni*8+2t, +1)
#pragma unroll
    for (int mi = 0; mi < 4; mi++) {
#pragma unroll
        for (int half = 0; half < 2; half++) {
            const int grow = row0 + wm + mi * 16 + g + half * 8;
            if (grow >= Nrows) continue;
#pragma unroll
            for (int ni = 0; ni < 4; ni++) {
                const int col = wn + ni * 8 + 2 * t;
                float c0 = acc[mi][ni][half * 2 + 0];
                float c1 = acc[mi][ni][half * 2 + 1];
                const size_t off = (size_t)grow * DH + col;
                if (mode == 0) {
                    c0 = sigmoidf_(c0 + bias_r[col]);
                    c1 = sigmoidf_(c1 + bias_r[col + 1]);
                    const float2 hh = *(const float2*)&hprev[off];
                    uint2 o;
                    o.x = f2tf32(c0 * hh.x);
                    o.y = f2tf32(c1 * hh.y);
                    *(uint2*)&g_rh32[off] = o;
                } else if (mode == 1) {
                    float2 o;
                    o.x = sigmoidf_(c0 + bias_z[col]);
                    o.y = sigmoidf_(c1 + bias_z[col + 1]);
                    *(float2*)&g_z[off] = o;
                } else if (mode == 2) {
                    __nv_bfloat162 p;
                    p.x = __float2bfloat16_rn(c0);
                    p.y = __float2bfloat16_rn(c1);
                    *(__nv_bfloat162*)&g_ybf[off] = p;
                } else {
                    *(float2*)&g_w[off] = make_float2(c0, c1);
                }
            }
        }
    }

    // producer: publish rh rows for this mx (release after all block stores)
    if (mode == 0) {
        __syncthreads();
        if (tid == 0) {
            asm volatile("st.global.release.gpu.b32 [%0], %1;"
                         :: "l"(&g_flag[mx]), "r"(1));
        }
    }
}

// ---------------------------------------------------------------------------
// Gather: one warp per node, sum neighbor y rows (bf16) -> g_agg (fp32).
// Runs on the side stream, overlapped with the mode-3 (w) GEMM launch.
// ---------------------------------------------------------------------------
__global__ __launch_bounds__(256) void gather_y()
{
    const int node = (blockIdx.x * blockDim.x + threadIdx.x) >> 5;
    const int lane = threadIdx.x & 31;
    if (node >= NN) return;

    const int off = g_off[node];
    const int deg = g_deg[node];

    float4 acc = make_float4(0.f, 0.f, 0.f, 0.f);
    auto addrow = [&](int s) {
        const uint2 v = *(const uint2*)&g_ybf[(size_t)s * DH + lane * 4];
        const float2 p0 = __bfloat1622float2(*(const __nv_bfloat162*)&v.x);
        const float2 p1 = __bfloat1622float2(*(const __nv_bfloat162*)&v.y);
        acc.x += p0.x; acc.y += p0.y; acc.z += p1.x; acc.w += p1.y;
    };

    int e = 0;
    for (; e + 4 <= deg; e += 4) {
        const int s0 = g_csr[off + e + 0];
        const int s1 = g_csr[off + e + 1];
        const int s2 = g_csr[off + e + 2];
        const int s3 = g_csr[off + e + 3];
        addrow(s0); addrow(s1); addrow(s2); addrow(s3);
    }
    for (; e < deg; e++) addrow(g_csr[off + e]);

    *(float4*)&g_agg[(size_t)node * DH + lane * 4] = acc;
}

// ---------------------------------------------------------------------------
// Final: out = (1-z) * (agg/max(deg,1) + b_l + w) + z * h_prev
// ---------------------------------------------------------------------------
__global__ __launch_bounds__(256) void final_kernel(
    const float* __restrict__ hprev, const float* __restrict__ b_l,
    float* __restrict__ out)
{
    const int i4 = blockIdx.x * blockDim.x + threadIdx.x;   // over NN*32
    if (i4 >= NN * (DH / 4)) return;
    const int node = i4 >> 5;
    const int c4   = i4 & 31;
    const size_t off = (size_t)i4 * 4;

    const float inv = 1.0f / (float)max(g_deg[node], 1);
    const float4 a  = *(const float4*)&g_agg[off];
    const float4 w  = *(const float4*)&g_w[off];
    const float4 z  = *(const float4*)&g_z[off];
    const float4 hh = *(const float4*)&hprev[off];
    const float4 bl = *(const float4*)&b_l[c4 * 4];

    float4 o;
    float n;
    n = fmaf(a.x, inv, bl.x) + w.x; o.x = (1.0f - z.x) * n + z.x * hh.x;
    n = fmaf(a.y, inv, bl.y) + w.y; o.y = (1.0f - z.y) * n + z.y * hh.y;
    n = fmaf(a.z, inv, bl.z) + w.z; o.z = (1.0f - z.z) * n + z.z * hh.z;
    n = fmaf(a.w, inv, bl.w) + w.w; o.w = (1.0f - z.w) * n + z.w * hh.w;
    *(float4*)&out[off] = o;
}

// ---------------------------------------------------------------------------
extern "C" void kernel_launch(void* const* d_in, const int* in_sizes, int n_in,
                              void* d_out, int out_size)
{
    const float* x    = (const float*)d_in[0];
    const int*   ei   = (const int*)  d_in[1];
    const float* h    = (const float*)d_in[2];
    const float* W_xr = (const float*)d_in[3];
    const float* b_xr = (const float*)d_in[4];
    const float* W_hr = (const float*)d_in[5];
    const float* W_xz = (const float*)d_in[6];
    const float* b_xz = (const float*)d_in[7];
    const float* W_hz = (const float*)d_in[8];
    const float* W_l  = (const float*)d_in[9];
    const float* b_l  = (const float*)d_in[10];
    const float* W_r  = (const float*)d_in[11];
    float* out = (float*)d_out;

    const uint32_t* xu = (const uint32_t*)x;
    const uint32_t* hu = (const uint32_t*)h;

    // One-time resources (created on the first, non-captured, call)
    static cudaStream_t sC = nullptr;
    static cudaEvent_t evRoot, evA, evGY;
    if (!sC) {
        cudaStreamCreateWithFlags(&sC, cudaStreamNonBlocking);
        cudaEventCreateWithFlags(&evRoot, cudaEventDisableTiming);
        cudaEventCreateWithFlags(&evA,    cudaEventDisableTiming);
        cudaEventCreateWithFlags(&evGY,   cudaEventDisableTiming);
    }

    // Fork: CSR build on side stream (hidden under prep + launch A)
    cudaEventRecord(evRoot, 0);
    cudaStreamWaitEvent(sC, evRoot, 0);
    zero_dc<<<(NN + 255) / 256, 256, 0, sC>>>();
    hist_kernel<<<(EE + 255) / 256, 256, 0, sC>>>(ei);
    scan_kernel<<<1, 1024, 0, sC>>>();
    fill_kernel<<<(EE + 255) / 256, 256, 0, sC>>>(ei);

    // Main stream: prep (zeroes flags) -> launch A (modes 0,1,2)
    prep_w<<<dim3(8, 4, 4), dim3(32, 8)>>>(W_xr, W_hr, W_xz, W_hz, W_l, W_r);
    gemm_modes<0><<<dim3(GG, 3), 256>>>(xu, hu, b_xr, b_xz, h, NN);
    cudaEventRecord(evA, 0);

    // Side stream: gather (needs y from A + CSR; CSR by stream order)
    cudaStreamWaitEvent(sC, evA, 0);
    gather_y<<<(NN * 32 + 255) / 256, 256, 0, sC>>>();
    cudaEventRecord(evGY, sC);

    // Main stream: launch B (mode 3, w) — overlaps gather_y
    gemm_modes<3><<<dim3(GG, 1), 256>>>(xu, hu, b_xr, b_xz, h, NN);

    // Join: final needs w (main) + agg (sC)
    cudaStreamWaitEvent(0, evGY, 0);
    final_kernel<<<(NN * (DH / 4) + 255) / 256, 256>>>(h, b_l, out);
}